// round 11
// baseline (speedup 1.0000x reference)
#include <cuda_runtime.h>
#include <math.h>

#define BATCH     32768
#define IN_DIM    64
#define NUM_BINS  10
#define EMBED_DIM 64
#define NTHRESH   9

#define TPB        256
#define K1_MBLK    256                  // minmax blocks (block 256 = bins+M)
#define T1         (K1_MBLK * TPB)      // 65536 threads -> 8 float4 per thread
#define NV         (BATCH * 16)         // 524288 float4s
#define SLOTS      32
#define K3_BLOCKS  512                  // 4096 warps * 8 rows = 32768

#define E8(x)   x,x,x,x,x,x,x,x
#define E64(x)  E8(x),E8(x),E8(x),E8(x),E8(x),E8(x),E8(x),E8(x)
#define E256(x) E64(x),E64(x),E64(x),E64(x)
#define E1K(x)  E256(x),E256(x),E256(x),E256(x)
#define E2K(x)  E1K(x),E1K(x)

// monotone float<->uint encoding (NaN-free data)
__device__ __forceinline__ unsigned fenc(float f) {
    unsigned u = __float_as_uint(f);
    return (u & 0x80000000u) ? ~u : (u | 0x80000000u);
}
__device__ __forceinline__ float fdec(unsigned e) {
    unsigned u = (e & 0x80000000u) ? (e ^ 0x80000000u) : ~e;
    return __uint_as_float(u);
}

// ---- scratch (device globals; no allocation allowed) ----
__device__ unsigned g_minenc[SLOTS * IN_DIM] = { E2K(0xFF800000u) };  // enc(+INF)
__device__ unsigned g_maxenc[SLOTS * IN_DIM] = { E2K(0x007FFFFFu) };  // enc(-INF)
__device__ float    g_bins[NTHRESH];
__device__ float    g_M[NUM_BINS * EMBED_DIM];
__device__ float4   g_nd4[32];          // per lane: {mn[2l], dn[2l], mn[2l+1], dn[2l+1]}
__device__ float2   g_D2[NTHRESH * 32]; // D[k][c] pairs
__device__ float2   g_base2[32];        // base[c] pairs

// ================= K1: min/max partials (MLP=8) + (block 256) bins + M =====
__global__ void __launch_bounds__(TPB)
k1_stats(const float4* __restrict__ x4,
         const float*  __restrict__ logits,
         const float*  __restrict__ embed,
         const float*  __restrict__ W) {
    const int tid  = threadIdx.x;
    const int lane = tid & 31;
    const int wrp  = tid >> 5;
    const int b    = blockIdx.x;

    __shared__ float smm[2][8][16][4];
    __shared__ float sWt[EMBED_DIM * 65];
    __shared__ float sEm[NUM_BINS * EMBED_DIM];
    __shared__ float sE[NUM_BINS];

    if (b < K1_MBLK) {
        // --- 8 independent front-batched float4 loads (col-group = tid%16) ---
        const int tg = b * TPB + tid;
        float4 v0 = x4[tg];
        float4 v1 = x4[tg + T1];
        float4 v2 = x4[tg + 2 * T1];
        float4 v3 = x4[tg + 3 * T1];
        float4 v4 = x4[tg + 4 * T1];
        float4 v5 = x4[tg + 5 * T1];
        float4 v6 = x4[tg + 6 * T1];
        float4 v7 = x4[tg + 7 * T1];

        float mn0 = fminf(fminf(fminf(v0.x, v1.x), fminf(v2.x, v3.x)),
                          fminf(fminf(v4.x, v5.x), fminf(v6.x, v7.x)));
        float mn1 = fminf(fminf(fminf(v0.y, v1.y), fminf(v2.y, v3.y)),
                          fminf(fminf(v4.y, v5.y), fminf(v6.y, v7.y)));
        float mn2 = fminf(fminf(fminf(v0.z, v1.z), fminf(v2.z, v3.z)),
                          fminf(fminf(v4.z, v5.z), fminf(v6.z, v7.z)));
        float mn3 = fminf(fminf(fminf(v0.w, v1.w), fminf(v2.w, v3.w)),
                          fminf(fminf(v4.w, v5.w), fminf(v6.w, v7.w)));
        float mx0 = fmaxf(fmaxf(fmaxf(v0.x, v1.x), fmaxf(v2.x, v3.x)),
                          fmaxf(fmaxf(v4.x, v5.x), fmaxf(v6.x, v7.x)));
        float mx1 = fmaxf(fmaxf(fmaxf(v0.y, v1.y), fmaxf(v2.y, v3.y)),
                          fmaxf(fmaxf(v4.y, v5.y), fmaxf(v6.y, v7.y)));
        float mx2 = fmaxf(fmaxf(fmaxf(v0.z, v1.z), fmaxf(v2.z, v3.z)),
                          fmaxf(fmaxf(v4.z, v5.z), fmaxf(v6.z, v7.z)));
        float mx3 = fmaxf(fmaxf(fmaxf(v0.w, v1.w), fmaxf(v2.w, v3.w)),
                          fmaxf(fmaxf(v4.w, v5.w), fmaxf(v6.w, v7.w)));

        mn0 = fminf(mn0, __shfl_down_sync(0xffffffffu, mn0, 16));
        mn1 = fminf(mn1, __shfl_down_sync(0xffffffffu, mn1, 16));
        mn2 = fminf(mn2, __shfl_down_sync(0xffffffffu, mn2, 16));
        mn3 = fminf(mn3, __shfl_down_sync(0xffffffffu, mn3, 16));
        mx0 = fmaxf(mx0, __shfl_down_sync(0xffffffffu, mx0, 16));
        mx1 = fmaxf(mx1, __shfl_down_sync(0xffffffffu, mx1, 16));
        mx2 = fmaxf(mx2, __shfl_down_sync(0xffffffffu, mx2, 16));
        mx3 = fmaxf(mx3, __shfl_down_sync(0xffffffffu, mx3, 16));
        if (lane < 16) {
            smm[0][wrp][lane][0] = mn0; smm[0][wrp][lane][1] = mn1;
            smm[0][wrp][lane][2] = mn2; smm[0][wrp][lane][3] = mn3;
            smm[1][wrp][lane][0] = mx0; smm[1][wrp][lane][1] = mx1;
            smm[1][wrp][lane][2] = mx2; smm[1][wrp][lane][3] = mx3;
        }
        __syncthreads();
        if (tid < IN_DIM) {
            const int g = tid >> 2, q = tid & 3;
            float a =  INFINITY, c = -INFINITY;
            #pragma unroll
            for (int w = 0; w < 8; w++) {
                a = fminf(a, smm[0][w][g][q]);
                c = fmaxf(c, smm[1][w][g][q]);
            }
            const int slot = (b & (SLOTS - 1)) * IN_DIM + tid;
            atomicMin(&g_minenc[slot], fenc(a));
            atomicMax(&g_maxenc[slot], fenc(c));
        }
    } else {
        // --- bins (warp 0, parallel exp) + M = embed @ W^T via smem staging ---
        if (wrp == 0) {
            float li = (lane < NUM_BINS) ? logits[lane] : -INFINITY;
            float m = li;
            #pragma unroll
            for (int d = 16; d >= 1; d >>= 1)
                m = fmaxf(m, __shfl_xor_sync(0xffffffffu, m, d));
            if (lane < NUM_BINS)
                sE[lane] = (float)exp((double)(li - m));   // correctly-rounded f32
            __syncwarp();
            if (lane == 0) {
                float s = 0.f;
                #pragma unroll
                for (int i = 0; i < NUM_BINS; i++) s += sE[i];   // fixed order
                float cum = 0.f;
                #pragma unroll
                for (int i = 0; i < NUM_BINS; i++) {
                    cum += __fdiv_rn(sE[i], s);                   // IEEE div
                    if (i < NTHRESH) g_bins[i] = cum;
                }
            }
        }
        #pragma unroll
        for (int i = tid; i < EMBED_DIM * EMBED_DIM; i += TPB) {
            const int f = i >> 6, e = i & 63;
            sWt[e * 65 + f] = W[i];           // coalesced read, conflict-free write
        }
        for (int i = tid; i < NUM_BINS * EMBED_DIM; i += TPB)
            sEm[i] = embed[i];
        __syncthreads();
        for (int i = tid; i < NUM_BINS * EMBED_DIM; i += TPB) {
            const int k = i >> 6, f = i & 63;
            const float* em = sEm + k * EMBED_DIM;
            float s = 0.f;
            #pragma unroll 16
            for (int e2 = 0; e2 < EMBED_DIM; e2++)
                s = fmaf(em[e2], sWt[e2 * 65 + f], s);
            g_M[i] = s;
        }
    }
}

// ================= K2: finalize mn/dn (+slot reset) + D/base precompute ====
__global__ void __launch_bounds__(1024)
k2_finalize(const float* __restrict__ bias) {
    const int tid = threadIdx.x;

    if (tid < 512) {
        const int col = tid >> 3;    // 0..63
        const int sub = tid & 7;
        unsigned emin = 0xFF800000u, emax = 0x007FFFFFu;
        #pragma unroll
        for (int s = sub; s < SLOTS; s += 8) {
            unsigned a = g_minenc[s * IN_DIM + col];
            unsigned c = g_maxenc[s * IN_DIM + col];
            emin = (a < emin) ? a : emin;
            emax = (c > emax) ? c : emax;
            g_minenc[s * IN_DIM + col] = 0xFF800000u;   // reset for next replay
            g_maxenc[s * IN_DIM + col] = 0x007FFFFFu;
        }
        #pragma unroll
        for (int d = 4; d >= 1; d >>= 1) {
            unsigned a = __shfl_xor_sync(0xffffffffu, emin, d);
            unsigned c = __shfl_xor_sync(0xffffffffu, emax, d);
            emin = (a < emin) ? a : emin;
            emax = (c > emax) ? c : emax;
        }
        if (sub == 0) {
            float a = fdec(emin), c = fdec(emax);
            float dn = (c - a) + 1e-6f;
            float* nd = (float*)g_nd4;
            nd[(col >> 1) * 4 + (col & 1) * 2]     = a;   // mn
            nd[(col >> 1) * 4 + (col & 1) * 2 + 1] = dn;  // dn
        }
    } else {
        const int i = tid - 512;           // 0..511
        float* gD = (float*)g_D2;
        gD[i] = g_M[i + 64] - g_M[i];
        if (i < 64)
            gD[512 + i] = g_M[512 + i + 64] - g_M[512 + i];
        if (i >= 64 && i < 128) {
            const int c = i - 64;
            ((float*)g_base2)[c] = 64.f * (g_M[c] + bias[c]);
        }
    }
}

// ================= K3: main — 8 rows per warp, MLP=8, no loops ==============
__global__ void __launch_bounds__(TPB)
k3_main(const float* __restrict__ x, float* __restrict__ out) {
    const int lane = threadIdx.x & 31;
    const int wrp  = threadIdx.x >> 5;
    const int w    = blockIdx.x * 8 + wrp;     // 0..4095
    const int r    = w * 8;

    const float4 nd = g_nd4[lane];
    const float mn0 = nd.x, dn0 = nd.y, mn1 = nd.z, dn1 = nd.w;

    float bins[NTHRESH];
    #pragma unroll
    for (int k = 0; k < NTHRESH; k++) bins[k] = g_bins[k];

    float2 Dv[NTHRESH];
    #pragma unroll
    for (int k = 0; k < NTHRESH; k++) Dv[k] = g_D2[k * 32 + lane];

    const float2 bs = g_base2[lane];

    const float2* __restrict__ xp = (const float2*)x + (size_t)r * 32 + lane;
    // all 8 row loads issued up front (MLP = 8)
    float2 v0 = xp[0];
    float2 v1 = xp[32];
    float2 v2 = xp[64];
    float2 v3 = xp[96];
    float2 v4 = xp[128];
    float2 v5 = xp[160];
    float2 v6 = xp[192];
    float2 v7 = xp[224];

    const unsigned KM = 0x4B400000u;
    const float    KC = 12582912.0f;
    float2* op = (float2*)out + (size_t)r * 32 + lane;

    // -------- group A: rows 0..3 --------
    {
        float xa0 = __fdiv_rn(v0.x - mn0, dn0), xa1 = __fdiv_rn(v0.y - mn1, dn1);
        float xb0 = __fdiv_rn(v1.x - mn0, dn0), xb1 = __fdiv_rn(v1.y - mn1, dn1);
        float xc0 = __fdiv_rn(v2.x - mn0, dn0), xc1 = __fdiv_rn(v2.y - mn1, dn1);
        float xd0 = __fdiv_rn(v3.x - mn0, dn0), xd1 = __fdiv_rn(v3.y - mn1, dn1);

        unsigned qa0 = 0, qa1 = 0, qb0 = 0, qb1 = 0;
        unsigned qc0 = 0, qc1 = 0, qd0 = 0, qd1 = 0, q2 = 0;
        #pragma unroll
        for (int k = 0; k < 4; k++) {
            const unsigned wgt = 1u << (8 * k);
            qa0 += (xa0 > bins[k]) ? wgt : 0u;  qa0 += (xa1 > bins[k]) ? wgt : 0u;
            qb0 += (xb0 > bins[k]) ? wgt : 0u;  qb0 += (xb1 > bins[k]) ? wgt : 0u;
            qc0 += (xc0 > bins[k]) ? wgt : 0u;  qc0 += (xc1 > bins[k]) ? wgt : 0u;
            qd0 += (xd0 > bins[k]) ? wgt : 0u;  qd0 += (xd1 > bins[k]) ? wgt : 0u;
        }
        #pragma unroll
        for (int k = 4; k < 8; k++) {
            const unsigned wgt = 1u << (8 * (k - 4));
            qa1 += (xa0 > bins[k]) ? wgt : 0u;  qa1 += (xa1 > bins[k]) ? wgt : 0u;
            qb1 += (xb0 > bins[k]) ? wgt : 0u;  qb1 += (xb1 > bins[k]) ? wgt : 0u;
            qc1 += (xc0 > bins[k]) ? wgt : 0u;  qc1 += (xc1 > bins[k]) ? wgt : 0u;
            qd1 += (xd0 > bins[k]) ? wgt : 0u;  qd1 += (xd1 > bins[k]) ? wgt : 0u;
        }
        q2 += (xa0 > bins[8]) ? 0x00000001u : 0u;  q2 += (xa1 > bins[8]) ? 0x00000001u : 0u;
        q2 += (xb0 > bins[8]) ? 0x00000100u : 0u;  q2 += (xb1 > bins[8]) ? 0x00000100u : 0u;
        q2 += (xc0 > bins[8]) ? 0x00010000u : 0u;  q2 += (xc1 > bins[8]) ? 0x00010000u : 0u;
        q2 += (xd0 > bins[8]) ? 0x01000000u : 0u;  q2 += (xd1 > bins[8]) ? 0x01000000u : 0u;

        qa0 = __reduce_add_sync(0xffffffffu, qa0);
        qa1 = __reduce_add_sync(0xffffffffu, qa1);
        qb0 = __reduce_add_sync(0xffffffffu, qb0);
        qb1 = __reduce_add_sync(0xffffffffu, qb1);
        qc0 = __reduce_add_sync(0xffffffffu, qc0);
        qc1 = __reduce_add_sync(0xffffffffu, qc1);
        qd0 = __reduce_add_sync(0xffffffffu, qd0);
        qd1 = __reduce_add_sync(0xffffffffu, qd1);
        q2  = __reduce_add_sync(0xffffffffu, q2);

        float a0 = bs.x, a1 = bs.y, b0 = bs.x, b1 = bs.y;
        float cc0 = bs.x, cc1 = bs.y, d0 = bs.x, d1 = bs.y;
        #pragma unroll
        for (int k = 0; k < 9; k++) {
            unsigned ua = (k < 4) ? __byte_perm(qa0, KM, 0x7640 + k)
                        : (k < 8) ? __byte_perm(qa1, KM, 0x7640 + (k - 4))
                                  : __byte_perm(q2,  KM, 0x7640);
            unsigned ub = (k < 4) ? __byte_perm(qb0, KM, 0x7640 + k)
                        : (k < 8) ? __byte_perm(qb1, KM, 0x7640 + (k - 4))
                                  : __byte_perm(q2,  KM, 0x7641);
            unsigned uc = (k < 4) ? __byte_perm(qc0, KM, 0x7640 + k)
                        : (k < 8) ? __byte_perm(qc1, KM, 0x7640 + (k - 4))
                                  : __byte_perm(q2,  KM, 0x7642);
            unsigned ud = (k < 4) ? __byte_perm(qd0, KM, 0x7640 + k)
                        : (k < 8) ? __byte_perm(qd1, KM, 0x7640 + (k - 4))
                                  : __byte_perm(q2,  KM, 0x7643);
            float fa = __uint_as_float(ua) - KC;
            float fb = __uint_as_float(ub) - KC;
            float fc = __uint_as_float(uc) - KC;
            float fd = __uint_as_float(ud) - KC;
            a0  = fmaf(fa, Dv[k].x, a0);   a1  = fmaf(fa, Dv[k].y, a1);
            b0  = fmaf(fb, Dv[k].x, b0);   b1  = fmaf(fb, Dv[k].y, b1);
            cc0 = fmaf(fc, Dv[k].x, cc0);  cc1 = fmaf(fc, Dv[k].y, cc1);
            d0  = fmaf(fd, Dv[k].x, d0);   d1  = fmaf(fd, Dv[k].y, d1);
        }
        op[0]  = make_float2(a0, a1);
        op[32] = make_float2(b0, b1);
        op[64] = make_float2(cc0, cc1);
        op[96] = make_float2(d0, d1);
    }

    // -------- group B: rows 4..7 --------
    {
        float xa0 = __fdiv_rn(v4.x - mn0, dn0), xa1 = __fdiv_rn(v4.y - mn1, dn1);
        float xb0 = __fdiv_rn(v5.x - mn0, dn0), xb1 = __fdiv_rn(v5.y - mn1, dn1);
        float xc0 = __fdiv_rn(v6.x - mn0, dn0), xc1 = __fdiv_rn(v6.y - mn1, dn1);
        float xd0 = __fdiv_rn(v7.x - mn0, dn0), xd1 = __fdiv_rn(v7.y - mn1, dn1);

        unsigned qa0 = 0, qa1 = 0, qb0 = 0, qb1 = 0;
        unsigned qc0 = 0, qc1 = 0, qd0 = 0, qd1 = 0, q2 = 0;
        #pragma unroll
        for (int k = 0; k < 4; k++) {
            const unsigned wgt = 1u << (8 * k);
            qa0 += (xa0 > bins[k]) ? wgt : 0u;  qa0 += (xa1 > bins[k]) ? wgt : 0u;
            qb0 += (xb0 > bins[k]) ? wgt : 0u;  qb0 += (xb1 > bins[k]) ? wgt : 0u;
            qc0 += (xc0 > bins[k]) ? wgt : 0u;  qc0 += (xc1 > bins[k]) ? wgt : 0u;
            qd0 += (xd0 > bins[k]) ? wgt : 0u;  qd0 += (xd1 > bins[k]) ? wgt : 0u;
        }
        #pragma unroll
        for (int k = 4; k < 8; k++) {
            const unsigned wgt = 1u << (8 * (k - 4));
            qa1 += (xa0 > bins[k]) ? wgt : 0u;  qa1 += (xa1 > bins[k]) ? wgt : 0u;
            qb1 += (xb0 > bins[k]) ? wgt : 0u;  qb1 += (xb1 > bins[k]) ? wgt : 0u;
            qc1 += (xc0 > bins[k]) ? wgt : 0u;  qc1 += (xc1 > bins[k]) ? wgt : 0u;
            qd1 += (xd0 > bins[k]) ? wgt : 0u;  qd1 += (xd1 > bins[k]) ? wgt : 0u;
        }
        q2 += (xa0 > bins[8]) ? 0x00000001u : 0u;  q2 += (xa1 > bins[8]) ? 0x00000001u : 0u;
        q2 += (xb0 > bins[8]) ? 0x00000100u : 0u;  q2 += (xb1 > bins[8]) ? 0x00000100u : 0u;
        q2 += (xc0 > bins[8]) ? 0x00010000u : 0u;  q2 += (xc1 > bins[8]) ? 0x00010000u : 0u;
        q2 += (xd0 > bins[8]) ? 0x01000000u : 0u;  q2 += (xd1 > bins[8]) ? 0x01000000u : 0u;

        qa0 = __reduce_add_sync(0xffffffffu, qa0);
        qa1 = __reduce_add_sync(0xffffffffu, qa1);
        qb0 = __reduce_add_sync(0xffffffffu, qb0);
        qb1 = __reduce_add_sync(0xffffffffu, qb1);
        qc0 = __reduce_add_sync(0xffffffffu, qc0);
        qc1 = __reduce_add_sync(0xffffffffu, qc1);
        qd0 = __reduce_add_sync(0xffffffffu, qd0);
        qd1 = __reduce_add_sync(0xffffffffu, qd1);
        q2  = __reduce_add_sync(0xffffffffu, q2);

        float a0 = bs.x, a1 = bs.y, b0 = bs.x, b1 = bs.y;
        float cc0 = bs.x, cc1 = bs.y, d0 = bs.x, d1 = bs.y;
        #pragma unroll
        for (int k = 0; k < 9; k++) {
            unsigned ua = (k < 4) ? __byte_perm(qa0, KM, 0x7640 + k)
                        : (k < 8) ? __byte_perm(qa1, KM, 0x7640 + (k - 4))
                                  : __byte_perm(q2,  KM, 0x7640);
            unsigned ub = (k < 4) ? __byte_perm(qb0, KM, 0x7640 + k)
                        : (k < 8) ? __byte_perm(qb1, KM, 0x7640 + (k - 4))
                                  : __byte_perm(q2,  KM, 0x7641);
            unsigned uc = (k < 4) ? __byte_perm(qc0, KM, 0x7640 + k)
                        : (k < 8) ? __byte_perm(qc1, KM, 0x7640 + (k - 4))
                                  : __byte_perm(q2,  KM, 0x7642);
            unsigned ud = (k < 4) ? __byte_perm(qd0, KM, 0x7640 + k)
                        : (k < 8) ? __byte_perm(qd1, KM, 0x7640 + (k - 4))
                                  : __byte_perm(q2,  KM, 0x7643);
            float fa = __uint_as_float(ua) - KC;
            float fb = __uint_as_float(ub) - KC;
            float fc = __uint_as_float(uc) - KC;
            float fd = __uint_as_float(ud) - KC;
            a0  = fmaf(fa, Dv[k].x, a0);   a1  = fmaf(fa, Dv[k].y, a1);
            b0  = fmaf(fb, Dv[k].x, b0);   b1  = fmaf(fb, Dv[k].y, b1);
            cc0 = fmaf(fc, Dv[k].x, cc0);  cc1 = fmaf(fc, Dv[k].y, cc1);
            d0  = fmaf(fd, Dv[k].x, d0);   d1  = fmaf(fd, Dv[k].y, d1);
        }
        op[128] = make_float2(a0, a1);
        op[160] = make_float2(b0, b1);
        op[192] = make_float2(cc0, cc1);
        op[224] = make_float2(d0, d1);
    }
}

extern "C" void kernel_launch(void* const* d_in, const int* in_sizes, int n_in,
                              void* d_out, int out_size) {
    const float* x      = (const float*)d_in[0];
    const float* logits = (const float*)d_in[1];
    const float* embed  = (const float*)d_in[2];
    const float* W      = (const float*)d_in[3];
    const float* bias   = (const float*)d_in[4];
    float* out          = (float*)d_out;

    k1_stats<<<K1_MBLK + 1, TPB>>>((const float4*)x, logits, embed, W);
    k2_finalize<<<1, 1024>>>(bias);
    k3_main<<<K3_BLOCKS, TPB>>>(x, out);
}

// round 12
// speedup vs baseline: 1.0017x; 1.0017x over previous
#include <cuda_runtime.h>
#include <math.h>

#define BATCH     32768
#define IN_DIM    64
#define NUM_BINS  10
#define EMBED_DIM 64
#define NTHRESH   9

#define GRID   444                // 148 SMs * 3 blocks co-resident
#define TPB    256
#define MMB    443                // blocks 0..442 own rows; block 443 = bins+M
#define SLOTS  32
#define MAXR   74                 // max rows per block (32768/443 -> 73..74)

#define E8(x)   x,x,x,x,x,x,x,x
#define E64(x)  E8(x),E8(x),E8(x),E8(x),E8(x),E8(x),E8(x),E8(x)
#define E256(x) E64(x),E64(x),E64(x),E64(x)
#define E1K(x)  E256(x),E256(x),E256(x),E256(x)
#define E2K(x)  E1K(x),E1K(x)

__device__ __forceinline__ unsigned fenc(float f) {
    unsigned u = __float_as_uint(f);
    return (u & 0x80000000u) ? ~u : (u | 0x80000000u);
}
__device__ __forceinline__ float fdec(unsigned e) {
    unsigned u = (e & 0x80000000u) ? (e ^ 0x80000000u) : ~e;
    return __uint_as_float(u);
}

// ---- scratch (device globals; no allocation allowed) ----
__device__ unsigned g_minenc[SLOTS * IN_DIM] = { E2K(0xFF800000u) };  // enc(+INF)
__device__ unsigned g_maxenc[SLOTS * IN_DIM] = { E2K(0x007FFFFFu) };  // enc(-INF)
__device__ float    g_bins[NTHRESH];
__device__ float    g_M[NUM_BINS * EMBED_DIM];
__device__ float4   g_nd4[32];            // per lane: {mn0,dn0,mn1,dn1}
__device__ float2   g_D2[NTHRESH * 32];   // D[k] column pairs
__device__ float2   g_base2[32];          // base pairs
__device__ int      g_count;
__device__ unsigned g_release;

__global__ void __launch_bounds__(TPB, 3)
dybem_fused(const float*  __restrict__ x,
            const float*  __restrict__ logits,
            const float*  __restrict__ embed,
            const float*  __restrict__ W,
            const float*  __restrict__ bias,
            float*        __restrict__ out) {
    const int tid  = threadIdx.x;
    const int lane = tid & 31;
    const int wrp  = tid >> 5;
    const int b    = blockIdx.x;

    __shared__ float4   sX[MAXR * 16];         // this block's rows (18944 B)
    __shared__ float    smm[2][8][16][4];      // reduce scratch (also finalize)
    __shared__ unsigned sPm[2][4 * IN_DIM];    // finalize slot partials
    __shared__ float    sWt[EMBED_DIM * 65];   // M-block: W transposed, padded
    __shared__ float    sEm[NUM_BINS * EMBED_DIM];
    __shared__ float    sE[NUM_BINS];
    __shared__ unsigned s_snap;
    __shared__ int      s_ticket;

    if (tid == 0) s_snap = *(volatile unsigned*)&g_release;
    __syncthreads();

    const int r0    = (int)(((long long)b * BATCH) / MMB);       // valid for b<MMB
    const int r1    = (int)(((long long)(b + 1) * BATCH) / MMB);
    const int nrows = r1 - r0;                                   // 73 or 74

    // ================= PHASE 1 =================
    if (b < MMB) {
        // load own rows to smem + per-column-group min/max (col-group = tid%16)
        const float4* __restrict__ x4 = (const float4*)x + (size_t)r0 * 16;
        const int n16 = nrows * 16;          // 1168 or 1184 (>= 1024+tid range)
        float4 v0 = x4[tid];
        float4 v1 = x4[tid + 256];
        float4 v2 = x4[tid + 512];
        float4 v3 = x4[tid + 768];
        sX[tid]       = v0;
        sX[tid + 256] = v1;
        sX[tid + 512] = v2;
        sX[tid + 768] = v3;
        float mn0 = fminf(fminf(v0.x, v1.x), fminf(v2.x, v3.x));
        float mn1 = fminf(fminf(v0.y, v1.y), fminf(v2.y, v3.y));
        float mn2 = fminf(fminf(v0.z, v1.z), fminf(v2.z, v3.z));
        float mn3 = fminf(fminf(v0.w, v1.w), fminf(v2.w, v3.w));
        float mx0 = fmaxf(fmaxf(v0.x, v1.x), fmaxf(v2.x, v3.x));
        float mx1 = fmaxf(fmaxf(v0.y, v1.y), fmaxf(v2.y, v3.y));
        float mx2 = fmaxf(fmaxf(v0.z, v1.z), fmaxf(v2.z, v3.z));
        float mx3 = fmaxf(fmaxf(v0.w, v1.w), fmaxf(v2.w, v3.w));
        // tail (i = tid+1024): stride 256 keeps col-group == tid%16
        for (int i = tid + 1024; i < n16; i += 256) {
            float4 v = x4[i];
            sX[i] = v;
            mn0 = fminf(mn0, v.x); mx0 = fmaxf(mx0, v.x);
            mn1 = fminf(mn1, v.y); mx1 = fmaxf(mx1, v.y);
            mn2 = fminf(mn2, v.z); mx2 = fmaxf(mx2, v.z);
            mn3 = fminf(mn3, v.w); mx3 = fmaxf(mx3, v.w);
        }
        mn0 = fminf(mn0, __shfl_down_sync(0xffffffffu, mn0, 16));
        mn1 = fminf(mn1, __shfl_down_sync(0xffffffffu, mn1, 16));
        mn2 = fminf(mn2, __shfl_down_sync(0xffffffffu, mn2, 16));
        mn3 = fminf(mn3, __shfl_down_sync(0xffffffffu, mn3, 16));
        mx0 = fmaxf(mx0, __shfl_down_sync(0xffffffffu, mx0, 16));
        mx1 = fmaxf(mx1, __shfl_down_sync(0xffffffffu, mx1, 16));
        mx2 = fmaxf(mx2, __shfl_down_sync(0xffffffffu, mx2, 16));
        mx3 = fmaxf(mx3, __shfl_down_sync(0xffffffffu, mx3, 16));
        if (lane < 16) {
            smm[0][wrp][lane][0] = mn0; smm[0][wrp][lane][1] = mn1;
            smm[0][wrp][lane][2] = mn2; smm[0][wrp][lane][3] = mn3;
            smm[1][wrp][lane][0] = mx0; smm[1][wrp][lane][1] = mx1;
            smm[1][wrp][lane][2] = mx2; smm[1][wrp][lane][3] = mx3;
        }
        __syncthreads();
        if (tid < IN_DIM) {
            const int g = tid >> 2, q = tid & 3;
            float a =  INFINITY, c = -INFINITY;
            #pragma unroll
            for (int w = 0; w < 8; w++) {
                a = fminf(a, smm[0][w][g][q]);
                c = fmaxf(c, smm[1][w][g][q]);
            }
            const int slot = (b & (SLOTS - 1)) * IN_DIM + tid;
            atomicMin(&g_minenc[slot], fenc(a));
            atomicMax(&g_maxenc[slot], fenc(c));
        }
    } else {
        // --- block 443: bins (warp 0, parallel exp) + M = embed @ W^T ---
        if (wrp == 0) {
            float li = (lane < NUM_BINS) ? logits[lane] : -INFINITY;
            float m = li;
            #pragma unroll
            for (int d = 16; d >= 1; d >>= 1)
                m = fmaxf(m, __shfl_xor_sync(0xffffffffu, m, d));
            if (lane < NUM_BINS)
                sE[lane] = (float)exp((double)(li - m));   // correctly-rounded f32
            __syncwarp();
            if (lane == 0) {
                float s = 0.f;
                #pragma unroll
                for (int i = 0; i < NUM_BINS; i++) s += sE[i];   // fixed order
                float cum = 0.f;
                #pragma unroll
                for (int i = 0; i < NUM_BINS; i++) {
                    cum += __fdiv_rn(sE[i], s);                   // IEEE div
                    if (i < NTHRESH) g_bins[i] = cum;
                }
            }
        }
        #pragma unroll
        for (int i = tid; i < EMBED_DIM * EMBED_DIM; i += TPB) {
            const int f = i >> 6, e = i & 63;
            sWt[e * 65 + f] = W[i];           // coalesced read, conflict-free write
        }
        for (int i = tid; i < NUM_BINS * EMBED_DIM; i += TPB)
            sEm[i] = embed[i];
        __syncthreads();
        for (int i = tid; i < NUM_BINS * EMBED_DIM; i += TPB) {
            const int k = i >> 6, f = i & 63;
            const float* em = sEm + k * EMBED_DIM;
            float s = 0.f;
            #pragma unroll 16
            for (int e2 = 0; e2 < EMBED_DIM; e2++)
                s = fmaf(em[e2], sWt[e2 * 65 + f], s);
            g_M[i] = s;
        }
    }

    // ================= GRID BARRIER =================
    __threadfence();
    __syncthreads();
    if (tid == 0) s_ticket = atomicAdd(&g_count, 1);
    __syncthreads();

    if (s_ticket == GRID - 1) {
        __threadfence();  // acquire all slot atomics + g_bins + g_M
        // fold 32 slots with 4 threads/col, then 64-thread final fold
        {
            const int col = tid & 63, sub = tid >> 6;
            unsigned emin = 0xFF800000u, emax = 0x007FFFFFu;
            #pragma unroll
            for (int s = sub; s < SLOTS; s += 4) {
                unsigned a = *(volatile unsigned*)&g_minenc[s * IN_DIM + col];
                unsigned c = *(volatile unsigned*)&g_maxenc[s * IN_DIM + col];
                emin = (a < emin) ? a : emin;
                emax = (c > emax) ? c : emax;
                g_minenc[s * IN_DIM + col] = 0xFF800000u;   // reset for replay
                g_maxenc[s * IN_DIM + col] = 0x007FFFFFu;
            }
            sPm[0][sub * IN_DIM + col] = emin;
            sPm[1][sub * IN_DIM + col] = emax;
        }
        __syncthreads();
        if (tid < IN_DIM) {
            unsigned emin = sPm[0][tid], emax = sPm[1][tid];
            #pragma unroll
            for (int s = 1; s < 4; s++) {
                unsigned a = sPm[0][s * IN_DIM + tid];
                unsigned c = sPm[1][s * IN_DIM + tid];
                emin = (a < emin) ? a : emin;
                emax = (c > emax) ? c : emax;
            }
            float a = fdec(emin), c = fdec(emax);
            float dn = (c - a) + 1e-6f;
            float* nd = (float*)g_nd4;
            nd[(tid >> 1) * 4 + (tid & 1) * 2]     = a;
            nd[(tid >> 1) * 4 + (tid & 1) * 2 + 1] = dn;
        }
        // D and base (absorbs old K2)
        {
            float* gD = (float*)g_D2;
            for (int i = tid; i < NTHRESH * 64; i += TPB)
                gD[i] = g_M[i + 64] - g_M[i];
            if (tid < 64)
                ((float*)g_base2)[tid] = 64.f * (g_M[tid] + bias[tid]);
        }
        if (tid == 0) g_count = 0;
        __threadfence();
        __syncthreads();
        if (tid == 0) atomicAdd(&g_release, 1u);
    }

    if (tid == 0) {
        while (*(volatile unsigned*)&g_release == s_snap) { __nanosleep(32); }
    }
    __syncthreads();
    __threadfence();

    if (b >= MMB) return;   // bins+M block owns no rows

    // ================= PHASE 2 (rows from smem) =================
    const float4 nd = g_nd4[lane];
    const float mn0 = nd.x, dn0 = nd.y, mn1 = nd.z, dn1 = nd.w;

    float bins[NTHRESH];
    #pragma unroll
    for (int k = 0; k < NTHRESH; k++) bins[k] = g_bins[k];

    float2 Dv[NTHRESH];
    #pragma unroll
    for (int k = 0; k < NTHRESH; k++) Dv[k] = g_D2[k * 32 + lane];

    const float2 bs = g_base2[lane];

    const float* sXf = (const float*)sX;
    float2* __restrict__ out2 = (float2*)out;

    const unsigned KM = 0x4B400000u;
    const float    KC = 12582912.0f;

    int lr           = (wrp * nrows) >> 3;
    const int lr_end = ((wrp + 1) * nrows) >> 3;

    for (; lr + 4 <= lr_end; lr += 4) {
        float2 v0 = *(const float2*)&sXf[(lr + 0) * 64 + 2 * lane];
        float2 v1 = *(const float2*)&sXf[(lr + 1) * 64 + 2 * lane];
        float2 v2 = *(const float2*)&sXf[(lr + 2) * 64 + 2 * lane];
        float2 v3 = *(const float2*)&sXf[(lr + 3) * 64 + 2 * lane];

        float xa0 = __fdiv_rn(v0.x - mn0, dn0), xa1 = __fdiv_rn(v0.y - mn1, dn1);
        float xb0 = __fdiv_rn(v1.x - mn0, dn0), xb1 = __fdiv_rn(v1.y - mn1, dn1);
        float xc0 = __fdiv_rn(v2.x - mn0, dn0), xc1 = __fdiv_rn(v2.y - mn1, dn1);
        float xd0 = __fdiv_rn(v3.x - mn0, dn0), xd1 = __fdiv_rn(v3.y - mn1, dn1);

        unsigned qa0 = 0, qa1 = 0, qb0 = 0, qb1 = 0;
        unsigned qc0 = 0, qc1 = 0, qd0 = 0, qd1 = 0, q2 = 0;
        #pragma unroll
        for (int k = 0; k < 4; k++) {
            const unsigned wgt = 1u << (8 * k);
            qa0 += (xa0 > bins[k]) ? wgt : 0u;  qa0 += (xa1 > bins[k]) ? wgt : 0u;
            qb0 += (xb0 > bins[k]) ? wgt : 0u;  qb0 += (xb1 > bins[k]) ? wgt : 0u;
            qc0 += (xc0 > bins[k]) ? wgt : 0u;  qc0 += (xc1 > bins[k]) ? wgt : 0u;
            qd0 += (xd0 > bins[k]) ? wgt : 0u;  qd0 += (xd1 > bins[k]) ? wgt : 0u;
        }
        #pragma unroll
        for (int k = 4; k < 8; k++) {
            const unsigned wgt = 1u << (8 * (k - 4));
            qa1 += (xa0 > bins[k]) ? wgt : 0u;  qa1 += (xa1 > bins[k]) ? wgt : 0u;
            qb1 += (xb0 > bins[k]) ? wgt : 0u;  qb1 += (xb1 > bins[k]) ? wgt : 0u;
            qc1 += (xc0 > bins[k]) ? wgt : 0u;  qc1 += (xc1 > bins[k]) ? wgt : 0u;
            qd1 += (xd0 > bins[k]) ? wgt : 0u;  qd1 += (xd1 > bins[k]) ? wgt : 0u;
        }
        q2 += (xa0 > bins[8]) ? 0x00000001u : 0u;  q2 += (xa1 > bins[8]) ? 0x00000001u : 0u;
        q2 += (xb0 > bins[8]) ? 0x00000100u : 0u;  q2 += (xb1 > bins[8]) ? 0x00000100u : 0u;
        q2 += (xc0 > bins[8]) ? 0x00010000u : 0u;  q2 += (xc1 > bins[8]) ? 0x00010000u : 0u;
        q2 += (xd0 > bins[8]) ? 0x01000000u : 0u;  q2 += (xd1 > bins[8]) ? 0x01000000u : 0u;

        qa0 = __reduce_add_sync(0xffffffffu, qa0);
        qa1 = __reduce_add_sync(0xffffffffu, qa1);
        qb0 = __reduce_add_sync(0xffffffffu, qb0);
        qb1 = __reduce_add_sync(0xffffffffu, qb1);
        qc0 = __reduce_add_sync(0xffffffffu, qc0);
        qc1 = __reduce_add_sync(0xffffffffu, qc1);
        qd0 = __reduce_add_sync(0xffffffffu, qd0);
        qd1 = __reduce_add_sync(0xffffffffu, qd1);
        q2  = __reduce_add_sync(0xffffffffu, q2);

        float a0 = bs.x, a1 = bs.y, b0 = bs.x, b1 = bs.y;
        float cc0 = bs.x, cc1 = bs.y, d0 = bs.x, d1 = bs.y;
        #pragma unroll
        for (int k = 0; k < 9; k++) {
            unsigned ua = (k < 4) ? __byte_perm(qa0, KM, 0x7640 + k)
                        : (k < 8) ? __byte_perm(qa1, KM, 0x7640 + (k - 4))
                                  : __byte_perm(q2,  KM, 0x7640);
            unsigned ub = (k < 4) ? __byte_perm(qb0, KM, 0x7640 + k)
                        : (k < 8) ? __byte_perm(qb1, KM, 0x7640 + (k - 4))
                                  : __byte_perm(q2,  KM, 0x7641);
            unsigned uc = (k < 4) ? __byte_perm(qc0, KM, 0x7640 + k)
                        : (k < 8) ? __byte_perm(qc1, KM, 0x7640 + (k - 4))
                                  : __byte_perm(q2,  KM, 0x7642);
            unsigned ud = (k < 4) ? __byte_perm(qd0, KM, 0x7640 + k)
                        : (k < 8) ? __byte_perm(qd1, KM, 0x7640 + (k - 4))
                                  : __byte_perm(q2,  KM, 0x7643);
            float fa = __uint_as_float(ua) - KC;
            float fb = __uint_as_float(ub) - KC;
            float fc = __uint_as_float(uc) - KC;
            float fd = __uint_as_float(ud) - KC;
            a0  = fmaf(fa, Dv[k].x, a0);   a1  = fmaf(fa, Dv[k].y, a1);
            b0  = fmaf(fb, Dv[k].x, b0);   b1  = fmaf(fb, Dv[k].y, b1);
            cc0 = fmaf(fc, Dv[k].x, cc0);  cc1 = fmaf(fc, Dv[k].y, cc1);
            d0  = fmaf(fd, Dv[k].x, d0);   d1  = fmaf(fd, Dv[k].y, d1);
        }
        float2* op = out2 + (size_t)(r0 + lr) * 32 + lane;
        op[0]  = make_float2(a0, a1);
        op[32] = make_float2(b0, b1);
        op[64] = make_float2(cc0, cc1);
        op[96] = make_float2(d0, d1);
    }

    for (; lr < lr_end; lr++) {
        float2 v0 = *(const float2*)&sXf[lr * 64 + 2 * lane];
        float xa0 = __fdiv_rn(v0.x - mn0, dn0), xa1 = __fdiv_rn(v0.y - mn1, dn1);
        unsigned qa0 = 0, qa1 = 0, q2 = 0;
        #pragma unroll
        for (int k = 0; k < 4; k++) {
            const unsigned wgt = 1u << (8 * k);
            qa0 += (xa0 > bins[k]) ? wgt : 0u;  qa0 += (xa1 > bins[k]) ? wgt : 0u;
        }
        #pragma unroll
        for (int k = 4; k < 8; k++) {
            const unsigned wgt = 1u << (8 * (k - 4));
            qa1 += (xa0 > bins[k]) ? wgt : 0u;  qa1 += (xa1 > bins[k]) ? wgt : 0u;
        }
        q2 += (xa0 > bins[8]) ? 1u : 0u;  q2 += (xa1 > bins[8]) ? 1u : 0u;

        qa0 = __reduce_add_sync(0xffffffffu, qa0);
        qa1 = __reduce_add_sync(0xffffffffu, qa1);
        q2  = __reduce_add_sync(0xffffffffu, q2);

        float a0 = bs.x, a1 = bs.y;
        #pragma unroll
        for (int k = 0; k < 9; k++) {
            unsigned ua = (k < 4) ? __byte_perm(qa0, KM, 0x7640 + k)
                        : (k < 8) ? __byte_perm(qa1, KM, 0x7640 + (k - 4))
                                  : __byte_perm(q2,  KM, 0x7640);
            float fa = __uint_as_float(ua) - KC;
            a0 = fmaf(fa, Dv[k].x, a0);
            a1 = fmaf(fa, Dv[k].y, a1);
        }
        out2[(size_t)(r0 + lr) * 32 + lane] = make_float2(a0, a1);
    }
}

extern "C" void kernel_launch(void* const* d_in, const int* in_sizes, int n_in,
                              void* d_out, int out_size) {
    const float* x      = (const float*)d_in[0];
    const float* logits = (const float*)d_in[1];
    const float* embed  = (const float*)d_in[2];
    const float* W      = (const float*)d_in[3];
    const float* bias   = (const float*)d_in[4];
    float* out          = (float*)d_out;

    dybem_fused<<<GRID, TPB>>>(x, logits, embed, W, bias, out);
}